// round 1
// baseline (speedup 1.0000x reference)
#include <cuda_runtime.h>
#include <math.h>

#define B_    8
#define L_    4096
#define D_    384
#define DI_   768
#define S_    16
#define DTR_  24
#define KC_   4
#define NC_   40
#define T_    (B_*L_)          // 32768 tokens
#define XDN_  (DTR_ + 2*S_)    // 56
#define EPS_  1e-5f

// ---------------- scratch (static device globals; no allocation) ----------------
__device__ float g_xn   [T_ * D_];        // 50 MB   rmsnorm output
__device__ float g_xz   [T_ * 2 * DI_];   // 201 MB  xn @ W_in  (xp | z)
__device__ float g_xc   [T_ * DI_];       // 100 MB  conv+silu output
__device__ float g_xdbl [T_ * XDN_];      // 7 MB    xc @ W_xproj (dt_r | B | C)
__device__ float g_dt   [T_ * DI_];       // 100 MB  softplus(dt_r@W_dt + bias)
__device__ float g_y    [T_ * DI_];       // 100 MB  scan output
__device__ float g_ypart[64 * B_ * DI_];
__device__ float g_xpart[64 * B_ * D_];
__device__ float g_ym   [B_ * DI_];
__device__ float g_xmean[B_ * D_];
__device__ float g_pooled[B_ * D_];

// ---------------- RMSNorm: one block per token ----------------
__global__ void k_rmsnorm(const float* __restrict__ x, const float* __restrict__ ln_w) {
    int t = blockIdx.x;
    const float* xr = x + (size_t)t * D_;
    float ss = 0.f;
    for (int d = threadIdx.x; d < D_; d += 128) { float v = xr[d]; ss += v * v; }
    #pragma unroll
    for (int o = 16; o; o >>= 1) ss += __shfl_xor_sync(0xffffffffu, ss, o);
    __shared__ float sw[4];
    if ((threadIdx.x & 31) == 0) sw[threadIdx.x >> 5] = ss;
    __syncthreads();
    float tot = sw[0] + sw[1] + sw[2] + sw[3];
    float rs = rsqrtf(tot * (1.f / D_) + EPS_);
    for (int d = threadIdx.x; d < D_; d += 128)
        g_xn[(size_t)t * D_ + d] = xr[d] * rs * ln_w[d];
}

// ---------------- generic fp32 tiled GEMM: C[M,N] = A[M,K] @ Bm[K,N] ----------------
// BM=BN=64, BK=16, 256 threads, 4x4 per-thread tile. M%64==0, K%16==0 assumed; N guarded.
__global__ void k_gemm(const float* __restrict__ A, const float* __restrict__ Bm,
                       float* __restrict__ C, int M, int N, int K) {
    __shared__ float As[16][65];   // [k][m], padded
    __shared__ float Bs[16][64];   // [k][n]
    int tx = threadIdx.x & 15;     // n group
    int ty = threadIdx.x >> 4;     // m group
    int m0 = blockIdx.y * 64, n0 = blockIdx.x * 64;
    float acc[4][4] = {};
    int r = threadIdx.x >> 4, c = threadIdx.x & 15;   // A-load coords
    int rb = threadIdx.x >> 6, cb = threadIdx.x & 63; // B-load coords
    for (int k0 = 0; k0 < K; k0 += 16) {
        #pragma unroll
        for (int i = 0; i < 4; i++)
            As[c][r + 16 * i] = A[(size_t)(m0 + r + 16 * i) * K + k0 + c];
        #pragma unroll
        for (int i = 0; i < 4; i++) {
            int col = n0 + cb;
            Bs[rb + 4 * i][cb] = (col < N) ? Bm[(size_t)(k0 + rb + 4 * i) * N + col] : 0.f;
        }
        __syncthreads();
        #pragma unroll
        for (int kk = 0; kk < 16; kk++) {
            float a[4], b[4];
            #pragma unroll
            for (int i = 0; i < 4; i++) a[i] = As[kk][ty * 4 + i];
            #pragma unroll
            for (int j = 0; j < 4; j++) b[j] = Bs[kk][tx * 4 + j];
            #pragma unroll
            for (int i = 0; i < 4; i++)
                #pragma unroll
                for (int j = 0; j < 4; j++)
                    acc[i][j] = fmaf(a[i], b[j], acc[i][j]);
        }
        __syncthreads();
    }
    #pragma unroll
    for (int i = 0; i < 4; i++)
        #pragma unroll
        for (int j = 0; j < 4; j++) {
            int col = n0 + tx * 4 + j;
            if (col < N) C[(size_t)(m0 + ty * 4 + i) * N + col] = acc[i][j];
        }
}

// ---------------- causal depthwise conv (K=4) + SiLU ----------------
__global__ void k_conv(const float* __restrict__ conv_w, const float* __restrict__ conv_b) {
    int idx = blockIdx.x * 256 + threadIdx.x;
    if (idx >= T_ * DI_) return;
    int di = idx % DI_;
    int t  = idx / DI_;
    int l  = t & (L_ - 1);
    float acc = conv_b[di];
    #pragma unroll
    for (int k = 0; k < KC_; k++) {
        int ll = l - (KC_ - 1) + k;
        if (ll >= 0)
            acc = fmaf(conv_w[di * KC_ + k], g_xz[(size_t)(t - (KC_ - 1) + k) * (2 * DI_) + di], acc);
    }
    float sg = 1.f / (1.f + __expf(-acc));
    g_xc[(size_t)t * DI_ + di] = acc * sg;
}

// ---------------- dt = softplus(dt_r @ W_dt + bias); 8 tokens/block, 768 threads ----------------
__global__ void k_dt(const float* __restrict__ W_dt, const float* __restrict__ dt_bias) {
    __shared__ float s_dtr[8][DTR_];
    int t0 = blockIdx.x * 8;
    int tid = threadIdx.x;
    if (tid < 8 * DTR_) {
        int tt = tid / DTR_, rr = tid % DTR_;
        s_dtr[tt][rr] = g_xdbl[(size_t)(t0 + tt) * XDN_ + rr];
    }
    __syncthreads();
    int di = tid;
    float bias = dt_bias[di];
    float acc[8];
    #pragma unroll
    for (int tt = 0; tt < 8; tt++) acc[tt] = bias;
    for (int rr = 0; rr < DTR_; rr++) {
        float w = W_dt[rr * DI_ + di];
        #pragma unroll
        for (int tt = 0; tt < 8; tt++) acc[tt] = fmaf(s_dtr[tt][rr], w, acc[tt]);
    }
    #pragma unroll
    for (int tt = 0; tt < 8; tt++) {
        float v = acc[tt];
        float sp = (v > 20.f) ? v : log1pf(__expf(v));
        g_dt[(size_t)(t0 + tt) * DI_ + di] = sp;
    }
}

// ---------------- selective scan: block = (b, 32-di group), thread = (di_local, s) ----------------
__global__ void k_scan(const float* __restrict__ A_log) {
    int b  = blockIdx.x / (DI_ / 32);
    int dg = blockIdx.x % (DI_ / 32);
    int di_local = threadIdx.x >> 4;
    int s        = threadIdx.x & 15;
    int di = dg * 32 + di_local;
    float A = -__expf(A_log[di * S_ + s]);
    float h = 0.f;
    int tbase = b * L_;
    for (int l = 0; l < L_; l++) {
        int t = tbase + l;
        float Bv  = g_xdbl[(size_t)t * XDN_ + DTR_ + s];
        float Cv  = g_xdbl[(size_t)t * XDN_ + DTR_ + S_ + s];
        float dtv = g_dt[(size_t)t * DI_ + di];
        float xv  = g_xc[(size_t)t * DI_ + di];
        float dA  = __expf(dtv * A);
        h = fmaf(dA, h, dtv * xv * Bv);
        float yp = h * Cv;
        yp += __shfl_xor_sync(0xffffffffu, yp, 8);
        yp += __shfl_xor_sync(0xffffffffu, yp, 4);
        yp += __shfl_xor_sync(0xffffffffu, yp, 2);
        yp += __shfl_xor_sync(0xffffffffu, yp, 1);
        if (s == 0) g_y[(size_t)t * DI_ + di] = yp;
    }
}

// ---------------- partial mean over L of y2 = (y + xc*Dskip) * silu(z) ----------------
__global__ void k_ypart(const float* __restrict__ Dskip) {
    int di    = blockIdx.x * 256 + threadIdx.x;   // gridDim.x = 3
    int chunk = blockIdx.y;                       // 64 chunks of 64
    int b     = blockIdx.z;
    float ds = Dskip[di];
    float acc = 0.f;
    int t0 = b * L_ + chunk * 64;
    for (int i = 0; i < 64; i++) {
        int t = t0 + i;
        float z  = g_xz[(size_t)t * (2 * DI_) + DI_ + di];
        float sz = z / (1.f + __expf(-z));
        acc += (g_y[(size_t)t * DI_ + di] + g_xc[(size_t)t * DI_ + di] * ds) * sz;
    }
    g_ypart[(size_t)(chunk * B_ + b) * DI_ + di] = acc;
}

__global__ void k_ymean() {
    int i = blockIdx.x * 256 + threadIdx.x;       // B_*DI_ = 6144
    float acc = 0.f;
    for (int c = 0; c < 64; c++) acc += g_ypart[(size_t)c * B_ * DI_ + i];
    g_ym[i] = acc * (1.f / L_);
}

__global__ void k_xpart(const float* __restrict__ x) {
    int d = threadIdx.x;           // 384
    int chunk = blockIdx.x;        // 64
    int b = blockIdx.y;            // 8
    float acc = 0.f;
    int t0 = b * L_ + chunk * 64;
    for (int i = 0; i < 64; i++) acc += x[(size_t)(t0 + i) * D_ + d];
    g_xpart[(size_t)(chunk * B_ + b) * D_ + d] = acc;
}

__global__ void k_xmean() {
    int i = blockIdx.x * 256 + threadIdx.x;       // B_*D_ = 3072
    float acc = 0.f;
    for (int c = 0; c < 64; c++) acc += g_xpart[(size_t)c * B_ * D_ + i];
    g_xmean[i] = acc * (1.f / L_);
}

// ---------------- pooled = xmean + ym @ W_out  (linearity of mean over l) ----------------
__global__ void k_pooled(const float* __restrict__ W_out) {
    int d = threadIdx.x;   // 384
    int b = blockIdx.x;    // 8
    float acc = g_xmean[b * D_ + d];
    for (int di = 0; di < DI_; di++)
        acc = fmaf(g_ym[b * DI_ + di], W_out[(size_t)di * D_ + d], acc);
    g_pooled[b * D_ + d] = acc;
}

// ---------------- head: fc + batchnorm(batch stats) + relu + cls ----------------
__global__ void k_head(const float* __restrict__ W_fc, const float* __restrict__ b_fc,
                       const float* __restrict__ gamma, const float* __restrict__ beta,
                       const float* __restrict__ W_cls, const float* __restrict__ b_cls,
                       float* __restrict__ out) {
    __shared__ float sp[B_][D_];
    __shared__ float sh[B_][256];
    int tid = threadIdx.x;  // 256
    for (int i = tid; i < B_ * D_; i += 256) sp[i / D_][i % D_] = g_pooled[i];
    __syncthreads();
    int j = tid;
    float hv[B_];
    #pragma unroll
    for (int b = 0; b < B_; b++) hv[b] = b_fc[j];
    for (int k = 0; k < D_; k++) {
        float w = W_fc[(size_t)k * 256 + j];
        #pragma unroll
        for (int b = 0; b < B_; b++) hv[b] = fmaf(sp[b][k], w, hv[b]);
    }
    float mu = 0.f;
    #pragma unroll
    for (int b = 0; b < B_; b++) mu += hv[b];
    mu *= (1.f / B_);
    float var = 0.f;
    #pragma unroll
    for (int b = 0; b < B_; b++) { float dd = hv[b] - mu; var += dd * dd; }
    var *= (1.f / B_);
    float rs = rsqrtf(var + EPS_);
    float g = gamma[j], bt = beta[j];
    #pragma unroll
    for (int b = 0; b < B_; b++) {
        float v = (hv[b] - mu) * rs * g + bt;
        sh[b][j] = v > 0.f ? v : 0.f;
    }
    __syncthreads();
    for (int o = tid; o < B_ * NC_; o += 256) {
        int b = o / NC_, c = o % NC_;
        float acc = b_cls[c];
        for (int k = 0; k < 256; k++) acc = fmaf(sh[b][k], W_cls[k * NC_ + c], acc);
        out[o] = acc;
    }
}

// ---------------- launch ----------------
extern "C" void kernel_launch(void* const* d_in, const int* in_sizes, int n_in,
                              void* d_out, int out_size) {
    const float* x       = (const float*)d_in[0];
    const float* ln_w    = (const float*)d_in[1];
    const float* W_in    = (const float*)d_in[2];
    const float* conv_w  = (const float*)d_in[3];
    const float* conv_b  = (const float*)d_in[4];
    const float* W_xproj = (const float*)d_in[5];
    const float* W_dt    = (const float*)d_in[6];
    const float* dt_bias = (const float*)d_in[7];
    const float* A_log   = (const float*)d_in[8];
    const float* Dskip   = (const float*)d_in[9];
    const float* W_out   = (const float*)d_in[10];
    const float* W_fc    = (const float*)d_in[11];
    const float* b_fc    = (const float*)d_in[12];
    const float* bn_g    = (const float*)d_in[13];
    const float* bn_b    = (const float*)d_in[14];
    const float* W_cls   = (const float*)d_in[15];
    const float* b_cls   = (const float*)d_in[16];
    float* out = (float*)d_out;

    float *p_xn, *p_xz, *p_xc, *p_xdbl;
    cudaGetSymbolAddress((void**)&p_xn,   g_xn);
    cudaGetSymbolAddress((void**)&p_xz,   g_xz);
    cudaGetSymbolAddress((void**)&p_xc,   g_xc);
    cudaGetSymbolAddress((void**)&p_xdbl, g_xdbl);

    // 1. RMSNorm
    k_rmsnorm<<<T_, 128>>>(x, ln_w);
    // 2. xz = xn @ W_in   [32768 x 384 x 1536]
    k_gemm<<<dim3((2 * DI_ + 63) / 64, T_ / 64), 256>>>(p_xn, W_in, p_xz, T_, 2 * DI_, D_);
    // 3. causal depthwise conv + silu
    k_conv<<<(T_ * DI_ + 255) / 256, 256>>>(conv_w, conv_b);
    // 4. x_dbl = xc @ W_xproj   [32768 x 768 x 56]
    k_gemm<<<dim3(1, T_ / 64), 256>>>(p_xc, W_xproj, p_xdbl, T_, XDN_, DI_);
    // 5. dt = softplus(dt_r @ W_dt + bias)
    k_dt<<<T_ / 8, DI_>>>(W_dt, dt_bias);
    // 6. selective scan
    k_scan<<<B_ * (DI_ / 32), 512>>>(A_log);
    // 7. mean over l of gated output (two-pass deterministic)
    k_ypart<<<dim3(DI_ / 256, 64, B_), 256>>>(Dskip);
    k_ymean<<<(B_ * DI_) / 256, 256>>>();
    k_xpart<<<dim3(64, B_), D_>>>(x);
    k_xmean<<<(B_ * D_) / 256, 256>>>();
    // 8. pooled = xmean + ym @ W_out (output-GEMM folded through the mean)
    k_pooled<<<B_, D_>>>(W_out);
    // 9. fc + batchnorm + relu + classifier
    k_head<<<1, 256>>>(W_fc, b_fc, bn_g, bn_b, W_cls, b_cls, out);
}

// round 3
// speedup vs baseline: 2.5930x; 2.5930x over previous
#include <cuda_runtime.h>
#include <math.h>
#include <cstdint>

#define B_    8
#define L_    4096
#define D_    384
#define DI_   768
#define S_    16
#define DTR_  24
#define KC_   4
#define NC_   40
#define T_    (B_*L_)          // 32768 tokens
#define XDN_  (DTR_ + 2*S_)    // 56
#define NI_   (2*DI_)          // 1536
#define EPS_  1e-5f

// ======================= tf32 mma.sync helpers (sm_80+ PTX, HMMA on sm_103) =======================
__device__ __forceinline__ uint32_t f2tf32(float x) {
    uint32_t r; asm("cvt.rna.tf32.f32 %0, %1;" : "=r"(r) : "f"(x)); return r;
}
__device__ __forceinline__ void mma_tf32(float* c, const uint32_t* a, const uint32_t* b) {
    asm volatile(
        "mma.sync.aligned.m16n8k8.row.col.f32.tf32.tf32.f32 "
        "{%0,%1,%2,%3}, {%4,%5,%6,%7}, {%8,%9}, {%0,%1,%2,%3};\n"
        : "+f"(c[0]), "+f"(c[1]), "+f"(c[2]), "+f"(c[3])
        : "r"(a[0]), "r"(a[1]), "r"(a[2]), "r"(a[3]), "r"(b[0]), "r"(b[1]));
}

// ======================= scratch =======================
__device__ __align__(128) float g_xn   [T_ * D_];        // rmsnorm output
__device__ __align__(128) float g_xz   [T_ * NI_];       // xn @ W_in (xp | z)
__device__ __align__(128) float g_xc   [T_ * DI_];       // conv+silu output
__device__ __align__(128) float g_xdbl [T_ * XDN_];      // xc @ W_xproj
__device__ __align__(128) float g_dtx  [T_ * DI_ * 2];   // (dt, xc) interleaved
__device__ __align__(128) float g_bc   [T_ * S_ * 2];    // (B, C) interleaved
__device__ __align__(128) float g_y    [T_ * DI_];       // scan output
__device__ __align__(128) float g_wt   [NI_ * D_];       // W_in^T  [1536 x 384], k-contiguous
__device__ float g_ypart[64 * B_ * DI_];
__device__ float g_xpart[64 * B_ * D_];
__device__ float g_ym   [B_ * DI_];
__device__ float g_xmean[B_ * D_];
__device__ float g_pooled[B_ * D_];

// ======================= RMSNorm =======================
__global__ void k_rmsnorm(const float* __restrict__ x, const float* __restrict__ ln_w) {
    int t = blockIdx.x;
    const float* xr = x + (size_t)t * D_;
    float ss = 0.f;
    for (int d = threadIdx.x; d < D_; d += 128) { float v = xr[d]; ss += v * v; }
    #pragma unroll
    for (int o = 16; o; o >>= 1) ss += __shfl_xor_sync(0xffffffffu, ss, o);
    __shared__ float sw[4];
    if ((threadIdx.x & 31) == 0) sw[threadIdx.x >> 5] = ss;
    __syncthreads();
    float tot = sw[0] + sw[1] + sw[2] + sw[3];
    float rs = rsqrtf(tot * (1.f / D_) + EPS_);
    for (int d = threadIdx.x; d < D_; d += 128)
        g_xn[(size_t)t * D_ + d] = xr[d] * rs * ln_w[d];
}

// ======================= W_in transpose: g_wt[n][k] = W_in[k][n] =======================
__global__ void k_wt(const float* __restrict__ W_in) {
    __shared__ float tile[32][33];
    int k0 = blockIdx.x * 32, n0 = blockIdx.y * 32;
    int tx = threadIdx.x & 31, ty = threadIdx.x >> 5;
    for (int i = 0; i < 32; i += 8)
        tile[ty + i][tx] = W_in[(size_t)(k0 + ty + i) * NI_ + n0 + tx];
    __syncthreads();
    for (int i = 0; i < 32; i += 8)
        g_wt[(size_t)(n0 + ty + i) * D_ + k0 + tx] = tile[tx][ty + i];
}

// ======================= GEMM1: tf32 mma.sync, C[T,1536] = xn[T,384] @ W_in =======================
// Block 128x128x32, 256 threads (8 warps in 2x4), warp tile 64x32.
// smem rows padded to 36 words: fragment LDS addr = 4*gid + tig (mod 32) -> conflict-free.
#define GPAD_ 36

__global__ void __launch_bounds__(256, 2) k_gemm_tc(const float* __restrict__ A,
                                                    const float* __restrict__ Bt,
                                                    float* __restrict__ C) {
    __shared__ uint32_t sA[128 * GPAD_];
    __shared__ uint32_t sB[128 * GPAD_];
    int tid = threadIdx.x;
    int lane = tid & 31, wid = tid >> 5;
    int wm = wid >> 2, wn = wid & 3;      // 2 x 4 warp grid
    int gid = lane >> 2, tig = lane & 3;
    int m0 = blockIdx.y * 128, n0 = blockIdx.x * 128;

    float acc[4][4][4];
    #pragma unroll
    for (int i = 0; i < 4; i++)
        #pragma unroll
        for (int j = 0; j < 4; j++)
            #pragma unroll
            for (int q = 0; q < 4; q++) acc[i][j][q] = 0.f;

    int lr  = tid >> 3;        // load row (0..31 per 256-thread pass covers 32 rows? no: 1024 f4 / 256 = 4 passes)
    int lc4 = tid & 7;         // float4 column

    for (int k0 = 0; k0 < D_; k0 += 32) {
        #pragma unroll
        for (int i = 0; i < 4; i++) {
            int row = lr + i * 32;
            float4 v = *(const float4*)&A[(size_t)(m0 + row) * D_ + k0 + lc4 * 4];
            uint32_t* dst = &sA[row * GPAD_ + lc4 * 4];
            dst[0] = f2tf32(v.x); dst[1] = f2tf32(v.y); dst[2] = f2tf32(v.z); dst[3] = f2tf32(v.w);
        }
        #pragma unroll
        for (int i = 0; i < 4; i++) {
            int row = lr + i * 32;
            float4 v = *(const float4*)&Bt[(size_t)(n0 + row) * D_ + k0 + lc4 * 4];
            uint32_t* dst = &sB[row * GPAD_ + lc4 * 4];
            dst[0] = f2tf32(v.x); dst[1] = f2tf32(v.y); dst[2] = f2tf32(v.z); dst[3] = f2tf32(v.w);
        }
        __syncthreads();
        #pragma unroll
        for (int kk = 0; kk < 32; kk += 8) {
            uint32_t af[4][4], bf[4][2];
            #pragma unroll
            for (int mt = 0; mt < 4; mt++) {
                int r = wm * 64 + mt * 16 + gid;
                af[mt][0] = sA[r * GPAD_ + kk + tig];
                af[mt][1] = sA[(r + 8) * GPAD_ + kk + tig];
                af[mt][2] = sA[r * GPAD_ + kk + tig + 4];
                af[mt][3] = sA[(r + 8) * GPAD_ + kk + tig + 4];
            }
            #pragma unroll
            for (int nt = 0; nt < 4; nt++) {
                int r = wn * 32 + nt * 8 + gid;
                bf[nt][0] = sB[r * GPAD_ + kk + tig];
                bf[nt][1] = sB[r * GPAD_ + kk + tig + 4];
            }
            #pragma unroll
            for (int mt = 0; mt < 4; mt++)
                #pragma unroll
                for (int nt = 0; nt < 4; nt++)
                    mma_tf32(acc[mt][nt], af[mt], bf[nt]);
        }
        __syncthreads();
    }
    // epilogue: c0,c1 at (row, 2*tig), c2,c3 at (row+8, 2*tig)
    #pragma unroll
    for (int mt = 0; mt < 4; mt++) {
        int row = m0 + wm * 64 + mt * 16 + gid;
        #pragma unroll
        for (int nt = 0; nt < 4; nt++) {
            int col = n0 + wn * 32 + nt * 8 + 2 * tig;
            *(float2*)&C[(size_t)row * NI_ + col]       = make_float2(acc[mt][nt][0], acc[mt][nt][1]);
            *(float2*)&C[(size_t)(row + 8) * NI_ + col] = make_float2(acc[mt][nt][2], acc[mt][nt][3]);
        }
    }
}

// ======================= generic fp32 SIMT GEMM (for GEMM2) =======================
__global__ void k_gemm(const float* __restrict__ A, const float* __restrict__ Bm,
                       float* __restrict__ C, int M, int N, int K) {
    __shared__ float As[16][65];
    __shared__ float Bs[16][64];
    int tx = threadIdx.x & 15, ty = threadIdx.x >> 4;
    int m0 = blockIdx.y * 64, n0 = blockIdx.x * 64;
    float acc[4][4] = {};
    int r = threadIdx.x >> 4, c = threadIdx.x & 15;
    int rb = threadIdx.x >> 6, cb = threadIdx.x & 63;
    for (int k0 = 0; k0 < K; k0 += 16) {
        #pragma unroll
        for (int i = 0; i < 4; i++)
            As[c][r + 16 * i] = A[(size_t)(m0 + r + 16 * i) * K + k0 + c];
        #pragma unroll
        for (int i = 0; i < 4; i++) {
            int col = n0 + cb;
            Bs[rb + 4 * i][cb] = (col < N) ? Bm[(size_t)(k0 + rb + 4 * i) * N + col] : 0.f;
        }
        __syncthreads();
        #pragma unroll
        for (int kk = 0; kk < 16; kk++) {
            float a[4], b[4];
            #pragma unroll
            for (int i = 0; i < 4; i++) a[i] = As[kk][ty * 4 + i];
            #pragma unroll
            for (int j = 0; j < 4; j++) b[j] = Bs[kk][tx * 4 + j];
            #pragma unroll
            for (int i = 0; i < 4; i++)
                #pragma unroll
                for (int j = 0; j < 4; j++)
                    acc[i][j] = fmaf(a[i], b[j], acc[i][j]);
        }
        __syncthreads();
    }
    #pragma unroll
    for (int i = 0; i < 4; i++)
        #pragma unroll
        for (int j = 0; j < 4; j++) {
            int col = n0 + tx * 4 + j;
            if (col < N) C[(size_t)(m0 + ty * 4 + i) * N + col] = acc[i][j];
        }
}

// ======================= causal depthwise conv (K=4) + SiLU =======================
__global__ void k_conv(const float* __restrict__ conv_w, const float* __restrict__ conv_b) {
    int idx = blockIdx.x * 256 + threadIdx.x;
    if (idx >= T_ * DI_) return;
    int di = idx % DI_;
    int t  = idx / DI_;
    int l  = t & (L_ - 1);
    float acc = conv_b[di];
    #pragma unroll
    for (int k = 0; k < KC_; k++) {
        int ll = l - (KC_ - 1) + k;
        if (ll >= 0)
            acc = fmaf(conv_w[di * KC_ + k], g_xz[(size_t)(t - (KC_ - 1) + k) * NI_ + di], acc);
    }
    float sg = 1.f / (1.f + __expf(-acc));
    float v = acc * sg;
    g_xc[(size_t)t * DI_ + di] = v;
    g_dtx[((size_t)t * DI_ + di) * 2 + 1] = v;
}

// ======================= dt = softplus(dt_r @ W_dt + bias) =======================
__global__ void k_dt(const float* __restrict__ W_dt, const float* __restrict__ dt_bias) {
    __shared__ float s_dtr[8][DTR_];
    int t0 = blockIdx.x * 8;
    int tid = threadIdx.x;
    if (tid < 8 * DTR_) {
        int tt = tid / DTR_, rr = tid % DTR_;
        s_dtr[tt][rr] = g_xdbl[(size_t)(t0 + tt) * XDN_ + rr];
    }
    __syncthreads();
    int di = tid;
    float bias = dt_bias[di];
    float acc[8];
    #pragma unroll
    for (int tt = 0; tt < 8; tt++) acc[tt] = bias;
    for (int rr = 0; rr < DTR_; rr++) {
        float w = W_dt[rr * DI_ + di];
        #pragma unroll
        for (int tt = 0; tt < 8; tt++) acc[tt] = fmaf(s_dtr[tt][rr], w, acc[tt]);
    }
    #pragma unroll
    for (int tt = 0; tt < 8; tt++) {
        float v = acc[tt];
        float sp = (v > 20.f) ? v : log1pf(__expf(v));
        g_dtx[((size_t)(t0 + tt) * DI_ + di) * 2 + 0] = sp;
    }
}

// ======================= pack (B,C) interleaved =======================
__global__ void k_bcpack() {
    int idx = blockIdx.x * 256 + threadIdx.x;
    if (idx >= T_ * S_) return;
    int t = idx >> 4, s = idx & 15;
    float bv = g_xdbl[(size_t)t * XDN_ + DTR_ + s];
    float cv = g_xdbl[(size_t)t * XDN_ + DTR_ + S_ + s];
    ((float2*)g_bc)[idx] = make_float2(bv, cv);
}

// ======================= selective scan =======================
// grid (DI_/8 = 96, B_) = 768 blocks, 128 threads; thread = (di_local 0..7, s 0..15)
__global__ void __launch_bounds__(128) k_scan2(const float* __restrict__ A_log) {
    int dg = blockIdx.x, b = blockIdx.y;
    int di_local = threadIdx.x >> 4;
    int s        = threadIdx.x & 15;
    int di = dg * 8 + di_local;
    float A = -__expf(A_log[di * S_ + s]);
    float h = 0.f;
    size_t tbase = (size_t)b * L_;
    const float2* dtx = (const float2*)g_dtx;
    const float2* bc  = (const float2*)g_bc;
    for (int l = 0; l < L_; l += 4) {
        float2 dx[4], bcv[4];
        #pragma unroll
        for (int j = 0; j < 4; j++) {
            size_t t = tbase + l + j;
            dx[j]  = dtx[t * DI_ + di];
            bcv[j] = bc[t * S_ + s];
        }
        #pragma unroll
        for (int j = 0; j < 4; j++) {
            float dtv = dx[j].x, xv = dx[j].y;
            float dA = __expf(dtv * A);
            h = fmaf(dA, h, dtv * xv * bcv[j].x);
            float yp = h * bcv[j].y;
            yp += __shfl_xor_sync(0xffffffffu, yp, 8);
            yp += __shfl_xor_sync(0xffffffffu, yp, 4);
            yp += __shfl_xor_sync(0xffffffffu, yp, 2);
            yp += __shfl_xor_sync(0xffffffffu, yp, 1);
            if (s == 0) g_y[(tbase + l + j) * DI_ + di] = yp;
        }
    }
}

// ======================= pooled-mean pipeline =======================
__global__ void k_ypart(const float* __restrict__ Dskip) {
    int di    = blockIdx.x * 256 + threadIdx.x;
    int chunk = blockIdx.y;
    int b     = blockIdx.z;
    float ds = Dskip[di];
    float acc = 0.f;
    int t0 = b * L_ + chunk * 64;
    for (int i = 0; i < 64; i++) {
        int t = t0 + i;
        float z  = g_xz[(size_t)t * NI_ + DI_ + di];
        float sz = z / (1.f + __expf(-z));
        acc += (g_y[(size_t)t * DI_ + di] + g_xc[(size_t)t * DI_ + di] * ds) * sz;
    }
    g_ypart[(size_t)(chunk * B_ + b) * DI_ + di] = acc;
}
__global__ void k_ymean() {
    int i = blockIdx.x * 256 + threadIdx.x;
    float acc = 0.f;
    for (int c = 0; c < 64; c++) acc += g_ypart[(size_t)c * B_ * DI_ + i];
    g_ym[i] = acc * (1.f / L_);
}
__global__ void k_xpart(const float* __restrict__ x) {
    int d = threadIdx.x;
    int chunk = blockIdx.x;
    int b = blockIdx.y;
    float acc = 0.f;
    int t0 = b * L_ + chunk * 64;
    for (int i = 0; i < 64; i++) acc += x[(size_t)(t0 + i) * D_ + d];
    g_xpart[(size_t)(chunk * B_ + b) * D_ + d] = acc;
}
__global__ void k_xmean() {
    int i = blockIdx.x * 256 + threadIdx.x;
    float acc = 0.f;
    for (int c = 0; c < 64; c++) acc += g_xpart[(size_t)c * B_ * D_ + i];
    g_xmean[i] = acc * (1.f / L_);
}
__global__ void k_pooled(const float* __restrict__ W_out) {
    int d = threadIdx.x;
    int b = blockIdx.x;
    float acc = g_xmean[b * D_ + d];
    for (int di = 0; di < DI_; di++)
        acc = fmaf(g_ym[b * DI_ + di], W_out[(size_t)di * D_ + d], acc);
    g_pooled[b * D_ + d] = acc;
}

// ======================= head =======================
__global__ void k_head(const float* __restrict__ W_fc, const float* __restrict__ b_fc,
                       const float* __restrict__ gamma, const float* __restrict__ beta,
                       const float* __restrict__ W_cls, const float* __restrict__ b_cls,
                       float* __restrict__ out) {
    __shared__ float sp[B_][D_];
    __shared__ float sh[B_][256];
    int tid = threadIdx.x;
    for (int i = tid; i < B_ * D_; i += 256) sp[i / D_][i % D_] = g_pooled[i];
    __syncthreads();
    int j = tid;
    float hv[B_];
    #pragma unroll
    for (int b = 0; b < B_; b++) hv[b] = b_fc[j];
    for (int k = 0; k < D_; k++) {
        float w = W_fc[(size_t)k * 256 + j];
        #pragma unroll
        for (int b = 0; b < B_; b++) hv[b] = fmaf(sp[b][k], w, hv[b]);
    }
    float mu = 0.f;
    #pragma unroll
    for (int b = 0; b < B_; b++) mu += hv[b];
    mu *= (1.f / B_);
    float var = 0.f;
    #pragma unroll
    for (int b = 0; b < B_; b++) { float dd = hv[b] - mu; var += dd * dd; }
    var *= (1.f / B_);
    float rs = rsqrtf(var + EPS_);
    float g = gamma[j], bt = beta[j];
    #pragma unroll
    for (int b = 0; b < B_; b++) {
        float v = (hv[b] - mu) * rs * g + bt;
        sh[b][j] = v > 0.f ? v : 0.f;
    }
    __syncthreads();
    for (int o = tid; o < B_ * NC_; o += 256) {
        int b = o / NC_, c = o % NC_;
        float acc = b_cls[c];
        for (int k = 0; k < 256; k++) acc = fmaf(sh[b][k], W_cls[k * NC_ + c], acc);
        out[o] = acc;
    }
}

// ======================= launch =======================
extern "C" void kernel_launch(void* const* d_in, const int* in_sizes, int n_in,
                              void* d_out, int out_size) {
    const float* x       = (const float*)d_in[0];
    const float* ln_w    = (const float*)d_in[1];
    const float* W_in    = (const float*)d_in[2];
    const float* conv_w  = (const float*)d_in[3];
    const float* conv_b  = (const float*)d_in[4];
    const float* W_xproj = (const float*)d_in[5];
    const float* W_dt    = (const float*)d_in[6];
    const float* dt_bias = (const float*)d_in[7];
    const float* A_log   = (const float*)d_in[8];
    const float* Dskip   = (const float*)d_in[9];
    const float* W_out   = (const float*)d_in[10];
    const float* W_fc    = (const float*)d_in[11];
    const float* b_fc    = (const float*)d_in[12];
    const float* bn_g    = (const float*)d_in[13];
    const float* bn_b    = (const float*)d_in[14];
    const float* W_cls   = (const float*)d_in[15];
    const float* b_cls   = (const float*)d_in[16];
    float* out = (float*)d_out;

    float *p_xn, *p_xz, *p_xc, *p_xdbl, *p_wt;
    cudaGetSymbolAddress((void**)&p_xn,   g_xn);
    cudaGetSymbolAddress((void**)&p_xz,   g_xz);
    cudaGetSymbolAddress((void**)&p_xc,   g_xc);
    cudaGetSymbolAddress((void**)&p_xdbl, g_xdbl);
    cudaGetSymbolAddress((void**)&p_wt,   g_wt);

    // 1. RMSNorm + weight transpose
    k_rmsnorm<<<T_, 128>>>(x, ln_w);
    k_wt<<<dim3(D_ / 32, NI_ / 32), 256>>>(W_in);
    // 2. xz = xn @ W_in  — tf32 mma.sync [32768 x 1536 x 384]
    k_gemm_tc<<<dim3(NI_ / 128, T_ / 128), 256>>>(p_xn, p_wt, p_xz);
    // 3. causal depthwise conv + silu (also fills dtx.y)
    k_conv<<<(T_ * DI_ + 255) / 256, 256>>>(conv_w, conv_b);
    // 4. x_dbl = xc @ W_xproj  [32768 x 56 x 768]
    k_gemm<<<dim3(1, T_ / 64), 256>>>(p_xc, W_xproj, p_xdbl, T_, XDN_, DI_);
    // 5. dt (fills dtx.x) and BC pack
    k_dt<<<T_ / 8, DI_>>>(W_dt, dt_bias);
    k_bcpack<<<(T_ * S_ + 255) / 256, 256>>>();
    // 6. selective scan
    k_scan2<<<dim3(DI_ / 8, B_), 128>>>(A_log);
    // 7. means
    k_ypart<<<dim3(DI_ / 256, 64, B_), 256>>>(Dskip);
    k_ymean<<<(B_ * DI_) / 256, 256>>>();
    k_xpart<<<dim3(64, B_), D_>>>(x);
    k_xmean<<<(B_ * D_) / 256, 256>>>();
    // 8. pooled = xmean + ym @ W_out
    k_pooled<<<B_, D_>>>(W_out);
    // 9. head
    k_head<<<1, 256>>>(W_fc, b_fc, bn_g, bn_b, W_cls, b_cls, out);
}